// round 16
// baseline (speedup 1.0000x reference)
#include <cuda_runtime.h>
#include <cuda_bf16.h>
#include <cstdint>

// out[b,f] = -2.5*log10( sum_l A[b,l] * (trans[f,l]*w[l]) )
// wt_kernel -> g_wt bf16 [F,L] (2MB, L2-resident)
// gemm_log_kernel: R15 core (BM=32 BN=128 BK=64, 256 thr, grid 256, 2 CTAs/SM,
//   4 N-tiles x warp-pair K16 split, conflict-free 128B rows) with the
//   __syncthreads pipeline replaced by an mbarrier-decoupled per-tile ring:
//   4 slots x {full_a(256 STS arrivals), full_b(256 cp.async noinc arrivals),
//   empty(8 warp arrivals)}; warps drift up to 4 tiles.
// Ruled out: gmem split-K, 16-row tiles, BK=128/256B rows (conflicts), 64x64
//   tiles (spill), dedicated producer warps under joint barrier, 32x64 tiles,
//   wider in-warp ILP (neutral). tcgen05 rejected (compute_103 target).

#define BM 32
#define BN 128
#define BK 64
#define THREADS 256
#define B_ST   16384                  // BN*BK*2
#define ABF_ST 4096                   // BM*BK*2
#define OFF_ABF (4 * B_ST)            // B: 4 slots (64KB), A: 4 slots (16KB)
#define OFF_HDR (OFF_ABF + 4 * ABF_ST)
#define DYN_SMEM (OFF_HDR + 1024)     // ~81KB -> 2 CTAs/SM

__device__ __align__(16) __nv_bfloat16 g_wt[128 * 8192];

__global__ void wt_kernel(const float* __restrict__ trans,
                          const float* __restrict__ lam, int F, int L) {
    int i4 = blockIdx.x * blockDim.x + threadIdx.x;
    int total = (F * L) >> 2;
    if (i4 >= total) return;
    int l0 = (i4 % (L >> 2)) << 2;
    float4 t = reinterpret_cast<const float4*>(trans)[i4];
    float w[4];
#pragma unroll
    for (int j = 0; j < 4; j++) {
        int l = l0 + j;
        int hi = l + 1 < L ? l + 1 : L - 1;
        int lo = l > 0 ? l - 1 : 0;
        w[j] = 0.5f * (__ldg(lam + hi) - __ldg(lam + lo));
    }
    __nv_bfloat162 p0 = __floats2bfloat162_rn(t.x * w[0], t.y * w[1]);
    __nv_bfloat162 p1 = __floats2bfloat162_rn(t.z * w[2], t.w * w[3]);
    uint2 v = { reinterpret_cast<uint32_t&>(p0), reinterpret_cast<uint32_t&>(p1) };
    reinterpret_cast<uint2*>(g_wt)[i4] = v;
}

__device__ __forceinline__ uint32_t smem_u32(const void* p) {
    uint32_t a;
    asm("{ .reg .u64 t; cvta.to.shared.u64 t, %1; cvt.u32.u64 %0, t; }"
        : "=r"(a) : "l"(p));
    return a;
}
__device__ __forceinline__ void ldmx4(uint32_t* r, uint32_t addr) {
    asm volatile("ldmatrix.sync.aligned.m8n8.x4.shared.b16 {%0,%1,%2,%3}, [%4];\n"
                 : "=r"(r[0]), "=r"(r[1]), "=r"(r[2]), "=r"(r[3]) : "r"(addr));
}
__device__ __forceinline__ void mma16816(float* c, const uint32_t* a, const uint32_t* b) {
    asm volatile("mma.sync.aligned.m16n8k16.row.col.f32.bf16.bf16.f32 "
                 "{%0,%1,%2,%3}, {%4,%5,%6,%7}, {%8,%9}, {%0,%1,%2,%3};\n"
                 : "+f"(c[0]), "+f"(c[1]), "+f"(c[2]), "+f"(c[3])
                 : "r"(a[0]), "r"(a[1]), "r"(a[2]), "r"(a[3]), "r"(b[0]), "r"(b[1]));
}
__device__ __forceinline__ uint32_t packbf2(float x, float y) {
    __nv_bfloat162 h = __floats2bfloat162_rn(x, y);
    return reinterpret_cast<uint32_t&>(h);
}
__device__ __forceinline__ void cp16(uint32_t dst, const void* src) {
    asm volatile("cp.async.cg.shared.global [%0], [%1], 16;"
                 :: "r"(dst), "l"(src) : "memory");
}

#define MBARRIER_INIT(addr, cnt) \
    asm volatile("mbarrier.init.shared.b64 [%0], %1;" :: "r"(addr), "r"(cnt) : "memory")
#define MBARRIER_ARRIVE(addr) \
    asm volatile("mbarrier.arrive.release.cta.shared::cta.b64 _, [%0];" :: "r"(addr) : "memory")
#define CP_ARRIVE_NOINC(addr) \
    asm volatile("cp.async.mbarrier.arrive.noinc.shared.b64 [%0];" :: "r"(addr) : "memory")
#define MBARRIER_WAIT_PARITY(addr, par) do {                                   \
    uint32_t _m = (addr), _p = (par), _d;                                      \
    asm volatile("{\n\t.reg .pred p;\n\t"                                      \
        "mbarrier.try_wait.parity.acquire.cta.shared::cta.b64 p, [%1], %2;\n\t"\
        "selp.b32 %0, 1, 0, p;\n\t}" : "=r"(_d) : "r"(_m), "r"(_p) : "memory");\
    if (!_d) {                                                                 \
        asm volatile("{\n\t.reg .pred P1;\n\t"                                 \
        "WL_%=:\n\t"                                                           \
        "mbarrier.try_wait.parity.acquire.cta.shared::cta.b64 P1, [%0], %1, 0x989680;\n\t" \
        "@P1 bra.uni WD_%=;\n\t"                                               \
        "bra.uni WL_%=;\n\t"                                                   \
        "WD_%=:\n\t}" :: "r"(_m), "r"(_p) : "memory");                         \
    }                                                                          \
} while (0)

__global__ void __launch_bounds__(THREADS, 2)
gemm_log_kernel(const float* __restrict__ A, float* __restrict__ out, int K) {
    extern __shared__ char dynsmem[];
    const uint32_t base = (smem_u32(dynsmem) + 1023) & ~1023u;
    const uint32_t bB   = base;
    const uint32_t bAbf = base + OFF_ABF;
    const uint32_t hdr  = base + OFF_HDR;
    // 4 slots: full_a at hdr+0.., full_b at hdr+32.., empty at hdr+64..
#define FULL_A(s) (hdr + (uint32_t)(s) * 8)
#define FULL_B(s) (hdr + 32u + (uint32_t)(s) * 8)
#define EMPTY(s)  (hdr + 64u + (uint32_t)(s) * 8)

    const int tid  = threadIdx.x;
    const int lane = tid & 31;
    const int warp = tid >> 5;        // 0..7
    const int wt   = warp >> 1;       // N quarter 0..3
    const int kh   = warp & 1;        // k-half
    const size_t bm0 = (size_t)blockIdx.x * BM;
    const int NKT = K / BK;           // 128 tiles

    if (tid == 0) {
#pragma unroll
        for (int s = 0; s < 4; s++) {
            MBARRIER_INIT(FULL_A(s), 256);
            MBARRIER_INIT(FULL_B(s), 256);
            MBARRIER_INIT(EMPTY(s), 8);
        }
    }

    // ---- A staging: row ar = tid>>3 (0..31), 8 fp32 at cols 8*(tid&7)
    const int ar = tid >> 3, acg = tid & 7;
    const float4* aSrc4 = reinterpret_cast<const float4*>(A + (bm0 + ar) * (size_t)K)
                        + 2 * acg;
    const uint32_t abfrel = (uint32_t)ar * 128 + (uint32_t)((acg ^ (ar & 7)) * 16);

    // ---- B staging: 4 chunks/thread/tile, conflict-free 128B rows
    uint32_t brel[4];
    const __nv_bfloat16* bsrc[4];
#pragma unroll
    for (int j = 0; j < 4; j++) {
        int id = tid + 256 * j;
        int n = id >> 3, cc = id & 7;
        brel[j] = (uint32_t)(n * 128 + ((cc ^ (n & 7)) * 16));
        bsrc[j] = g_wt + (size_t)n * K + cc * 8;
    }

    // ---- warp tile: rows 0..31, cols [wt*32, wt*32+32); pair splits K16
    int arow[2], brow[2];
#pragma unroll
    for (int mi = 0; mi < 2; mi++) arow[mi] = mi * 16 + (lane & 15);
#pragma unroll
    for (int nj = 0; nj < 2; nj++) brow[nj] = wt * 32 + nj * 16 + ((lane >> 4) << 3) + (lane & 7);
    const int achalf = lane >> 4;
    const int bchalf = (lane >> 3) & 1;
    const int ks0 = kh * 2;

    float acc[2][4][4];
#pragma unroll
    for (int i = 0; i < 2; i++)
#pragma unroll
        for (int j = 0; j < 4; j++)
#pragma unroll
            for (int k = 0; k < 4; k++) acc[i][j][k] = 0.f;

    uint32_t fa[2][4];   // A register prefetch, 2 tiles in flight (pre-packed)

#define LOAD_TILE(T) do {                                                     \
        const float4* _p = aSrc4 + (size_t)(T) * (BK >> 2);                   \
        float4 _x = __ldg(_p), _y = __ldg(_p + 1);                            \
        uint32_t* _d = fa[(T) & 1];                                           \
        _d[0] = packbf2(_x.x, _x.y); _d[1] = packbf2(_x.z, _x.w);             \
        _d[2] = packbf2(_y.x, _y.y); _d[3] = packbf2(_y.z, _y.w);             \
    } while (0)

#define CONVERT_TILE(T) do {                                                  \
        const uint32_t _da = bAbf + (uint32_t)((T) & 3) * ABF_ST;             \
        uint32_t* _d = fa[(T) & 1];                                           \
        asm volatile("st.shared.v4.b32 [%0], {%1,%2,%3,%4};" ::               \
            "r"(_da + abfrel), "r"(_d[0]), "r"(_d[1]), "r"(_d[2]), "r"(_d[3]) \
            : "memory");                                                      \
    } while (0)

#define ISSUE_B_TILE(T, S) do {                                               \
        const uint32_t _bd = bB + (uint32_t)(S) * B_ST;                       \
        const size_t _o = (size_t)(T) * BK;                                   \
        _Pragma("unroll")                                                     \
        for (int _j = 0; _j < 4; _j++)                                        \
            cp16(_bd + brel[_j], bsrc[_j] + _o);                              \
    } while (0)

#define LDFRAG_TILE(AOFF, BOFF, a, b) do {                                    \
        _Pragma("unroll")                                                     \
        for (int _s = 0; _s < 2; _s++) {                                      \
            const int ks = ks0 + _s;                                          \
            const int _ca = ks * 2 + achalf;                                  \
            const int _cb = ks * 2 + bchalf;                                  \
            _Pragma("unroll")                                                 \
            for (int mi = 0; mi < 2; mi++)                                    \
                ldmx4((a)[_s][mi], (AOFF) + (uint32_t)(arow[mi] * 8 + (_ca ^ (arow[mi] & 7))) * 16); \
            _Pragma("unroll")                                                 \
            for (int nj = 0; nj < 2; nj++)                                    \
                ldmx4((b)[_s][nj], (BOFF) + (uint32_t)(brow[nj] * 8 + (_cb ^ (brow[nj] & 7))) * 16); \
        }                                                                     \
    } while (0)

#define MMA_TILE(a, b) do {                                                   \
        _Pragma("unroll")                                                     \
        for (int _s = 0; _s < 2; _s++)                                        \
            _Pragma("unroll")                                                 \
            for (int mi = 0; mi < 2; mi++)                                    \
                _Pragma("unroll")                                             \
                for (int nt = 0; nt < 4; nt++)                                \
                    mma16816(acc[mi][nt], (a)[_s][mi], &(b)[_s][nt >> 1][(nt & 1) * 2]); \
    } while (0)

    __syncthreads();                  // mbarrier init visible

    // ---------- prologue: stage tile 0 (slot 0, round 0) ----------
    LOAD_TILE(0);
    LOAD_TILE(1);
    ISSUE_B_TILE(0, 0);
    CP_ARRIVE_NOINC(FULL_B(0));
    CONVERT_TILE(0);
    MBARRIER_ARRIVE(FULL_A(0));

    // ---------- main loop: per-tile, mbarrier-decoupled ----------
    for (int kt = 0; kt < NKT; kt++) {
        if (kt + 2 < NKT) LOAD_TILE(kt + 2);       // into fa[kt&1] (tile kt converted)
        if (kt + 1 < NKT) {
            const int s1 = (kt + 1) & 3;
            const int r1 = (kt + 1) >> 2;
            if (kt + 1 >= 4) MBARRIER_WAIT_PARITY(EMPTY(s1), (r1 - 1) & 1);
            ISSUE_B_TILE(kt + 1, s1);
            CP_ARRIVE_NOINC(FULL_B(s1));
            CONVERT_TILE(kt + 1);
            MBARRIER_ARRIVE(FULL_A(s1));
        }
        const int s = kt & 3;
        const int r = kt >> 2;
        MBARRIER_WAIT_PARITY(FULL_B(s), r & 1);
        MBARRIER_WAIT_PARITY(FULL_A(s), r & 1);
        {
            uint32_t a[2][2][4], b[2][2][4];
            LDFRAG_TILE(bAbf + (uint32_t)s * ABF_ST, bB + (uint32_t)s * B_ST, a, b);
            MMA_TILE(a, b);
        }
        if (lane == 0) MBARRIER_ARRIVE(EMPTY(s));
    }

    // ---------- partner merge (kh=0 -> kh=1) via smem, then epilogue ----------
    __syncthreads();   // all consumption done; B ring free
    const uint32_t xb = bB + (uint32_t)wt * 4096 + (uint32_t)lane * 4;
    if (kh == 0) {
#pragma unroll
        for (int mi = 0; mi < 2; mi++)
#pragma unroll
            for (int nt = 0; nt < 4; nt++)
#pragma unroll
                for (int k = 0; k < 4; k++) {
                    const int e = mi * 16 + nt * 4 + k;
                    asm volatile("st.shared.f32 [%0], %1;"
                                 :: "r"(xb + (uint32_t)e * 128), "f"(acc[mi][nt][k])
                                 : "memory");
                }
    }
    __syncthreads();

    if (kh == 1) {
        const float C = -0.75257498915995302f;   // -2.5 / log2(10)
#pragma unroll
        for (int mi = 0; mi < 2; mi++) {
            const size_t row0 = bm0 + mi * 16 + (lane >> 2);
#pragma unroll
            for (int nt = 0; nt < 4; nt++) {
                float part[4];
#pragma unroll
                for (int k = 0; k < 4; k++) {
                    const int e = mi * 16 + nt * 4 + k;
                    asm volatile("ld.shared.f32 %0, [%1];"
                                 : "=f"(part[k]) : "r"(xb + (uint32_t)e * 128));
                }
                const int col = wt * 32 + nt * 8 + (lane & 3) * 2;
                float2 v0, v1;
                v0.x = C * __log2f(acc[mi][nt][0] + part[0]);
                v0.y = C * __log2f(acc[mi][nt][1] + part[1]);
                v1.x = C * __log2f(acc[mi][nt][2] + part[2]);
                v1.y = C * __log2f(acc[mi][nt][3] + part[3]);
                *reinterpret_cast<float2*>(out + row0 * BN + col)       = v0;
                *reinterpret_cast<float2*>(out + (row0 + 8) * BN + col) = v1;
            }
        }
    }
}

extern "C" void kernel_launch(void* const* d_in, const int* in_sizes, int n_in,
                              void* d_out, int out_size) {
    const float* l_target = (const float*)d_in[0];   // [B, L] fp32
    const float* trans    = (const float*)d_in[1];   // [F, L] fp32
    const float* lam      = (const float*)d_in[2];   // [L]    fp32

    const int L = in_sizes[2];
    const int F = in_sizes[1] / L;   // 128
    const int B = in_sizes[0] / L;   // 8192
    float* out = (float*)d_out;

    cudaFuncSetAttribute(gemm_log_kernel,
                         cudaFuncAttributeMaxDynamicSharedMemorySize, DYN_SMEM);

    int total4 = (F * L) >> 2;
    wt_kernel<<<(total4 + 255) / 256, 256>>>(trans, lam, F, L);
    gemm_log_kernel<<<B / BM, THREADS, DYN_SMEM>>>(l_target, out, L);
}

// round 17
// speedup vs baseline: 1.0120x; 1.0120x over previous
#include <cuda_runtime.h>
#include <cuda_bf16.h>
#include <cstdint>

// out[b,f] = -2.5*log10( sum_l A[b,l] * (trans[f,l]*w[l]) )
// wt_kernel -> g_wt bf16 [F,L] (2MB, L2-resident)
// gemm_log_kernel<K=8192>: BM=32 BN=128 BK=64, 256 thr, grid 256,
//   __launch_bounds__(256,3) -> 3 CTAs/SM (6 warps/SMSP, decoupled).
//   Register diet: compile-time K folds B offsets into immediates; per-tile
//   pipeline (fa[2] prefetch); B 3-slot ring (issue depth 2, wait_group 1);
//   Abf 2 slots; one __syncthreads per tile. R14 compute scheme
//   (4 N-quarters x warp-pair K16 split, conflict-free 128B rows).
// Ruled out: gmem split-K, 16-row tiles, BK=128/256B rows (conflicts), 64x64
//   tiles (spill), producer warps under joint barrier, 32x64 tiles, wider
//   in-warp ILP (neutral), per-tile mbarrier rings (R16). tcgen05 rejected
//   (compute_103 target).

#define BM 32
#define BN 128
#define BK 64
#define THREADS 256
#define B_ST   16384                  // BN*BK*2
#define ABF_ST 4096                   // BM*BK*2
#define OFF_ABF (3 * B_ST)            // B: 3 slots (48KB), Abf: 2 slots (8KB)
#define DYN_SMEM (OFF_ABF + 2 * ABF_ST + 1024)   // ~57KB -> 3 CTAs/SM

__device__ __align__(16) __nv_bfloat16 g_wt[128 * 8192];

__global__ void wt_kernel(const float* __restrict__ trans,
                          const float* __restrict__ lam, int F, int L) {
    int i4 = blockIdx.x * blockDim.x + threadIdx.x;
    int total = (F * L) >> 2;
    if (i4 >= total) return;
    int l0 = (i4 % (L >> 2)) << 2;
    float4 t = reinterpret_cast<const float4*>(trans)[i4];
    float w[4];
#pragma unroll
    for (int j = 0; j < 4; j++) {
        int l = l0 + j;
        int hi = l + 1 < L ? l + 1 : L - 1;
        int lo = l > 0 ? l - 1 : 0;
        w[j] = 0.5f * (__ldg(lam + hi) - __ldg(lam + lo));
    }
    __nv_bfloat162 p0 = __floats2bfloat162_rn(t.x * w[0], t.y * w[1]);
    __nv_bfloat162 p1 = __floats2bfloat162_rn(t.z * w[2], t.w * w[3]);
    uint2 v = { reinterpret_cast<uint32_t&>(p0), reinterpret_cast<uint32_t&>(p1) };
    reinterpret_cast<uint2*>(g_wt)[i4] = v;
}

__device__ __forceinline__ uint32_t smem_u32(const void* p) {
    uint32_t a;
    asm("{ .reg .u64 t; cvta.to.shared.u64 t, %1; cvt.u32.u64 %0, t; }"
        : "=r"(a) : "l"(p));
    return a;
}
__device__ __forceinline__ void ldmx4(uint32_t* r, uint32_t addr) {
    asm volatile("ldmatrix.sync.aligned.m8n8.x4.shared.b16 {%0,%1,%2,%3}, [%4];\n"
                 : "=r"(r[0]), "=r"(r[1]), "=r"(r[2]), "=r"(r[3]) : "r"(addr));
}
__device__ __forceinline__ void mma16816(float* c, const uint32_t* a, const uint32_t* b) {
    asm volatile("mma.sync.aligned.m16n8k16.row.col.f32.bf16.bf16.f32 "
                 "{%0,%1,%2,%3}, {%4,%5,%6,%7}, {%8,%9}, {%0,%1,%2,%3};\n"
                 : "+f"(c[0]), "+f"(c[1]), "+f"(c[2]), "+f"(c[3])
                 : "r"(a[0]), "r"(a[1]), "r"(a[2]), "r"(a[3]), "r"(b[0]), "r"(b[1]));
}
__device__ __forceinline__ uint32_t packbf2(float x, float y) {
    __nv_bfloat162 h = __floats2bfloat162_rn(x, y);
    return reinterpret_cast<uint32_t&>(h);
}
__device__ __forceinline__ void cp16(uint32_t dst, const void* src) {
    asm volatile("cp.async.cg.shared.global [%0], [%1], 16;"
                 :: "r"(dst), "l"(src) : "memory");
}
#define CP_COMMIT() asm volatile("cp.async.commit_group;" ::: "memory")
#define CP_WAIT1()  asm volatile("cp.async.wait_group 1;" ::: "memory")

template <int K>
__global__ void __launch_bounds__(THREADS, 3)
gemm_log_kernel(const float* __restrict__ A, float* __restrict__ out) {
    extern __shared__ char dynsmem[];
    const uint32_t base = (smem_u32(dynsmem) + 1023) & ~1023u;
    const uint32_t bB   = base;
    const uint32_t bAbf = base + OFF_ABF;

    const int tid  = threadIdx.x;
    const int lane = tid & 31;
    const int warp = tid >> 5;        // 0..7
    const int wt   = warp >> 1;       // N quarter 0..3
    const int kh   = warp & 1;        // k-half
    const size_t bm0 = (size_t)blockIdx.x * BM;
    constexpr int NKT = K / BK;       // 128 tiles

    // ---- A staging: row ar = tid>>3 (0..31), 8 fp32 at cols 8*(tid&7)
    const int ar = tid >> 3, acg = tid & 7;
    const float4* aSrc4 = reinterpret_cast<const float4*>(A + (bm0 + ar) * (size_t)K)
                        + 2 * acg;
    const uint32_t abfrel = (uint32_t)ar * 128 + (uint32_t)((acg ^ (ar & 7)) * 16);

    // ---- B staging: base chunk + compile-time strides (saves regs)
    // chunk j: row n = (tid>>3) + 32j, col chunk cc = tid&7 (same all j)
    //   brel_j = brel0 + 4096*j ; bsrc_j = bsrc0 + 32*K*j (elements)
    const uint32_t brel0 = (uint32_t)((tid >> 3) * 128 + (((tid & 7) ^ ((tid >> 3) & 7)) * 16));
    const __nv_bfloat16* bsrc0 = g_wt + (size_t)(tid >> 3) * K + (tid & 7) * 8;

    // ---- warp tile: rows 0..31, cols [wt*32, wt*32+32); pair splits K16
    int arow[2], brow[2];
#pragma unroll
    for (int mi = 0; mi < 2; mi++) arow[mi] = mi * 16 + (lane & 15);
#pragma unroll
    for (int nj = 0; nj < 2; nj++) brow[nj] = wt * 32 + nj * 16 + ((lane >> 4) << 3) + (lane & 7);
    const int achalf = lane >> 4;
    const int bchalf = (lane >> 3) & 1;
    const int ks0 = kh * 2;

    float acc[2][4][4];
#pragma unroll
    for (int i = 0; i < 2; i++)
#pragma unroll
        for (int j = 0; j < 4; j++)
#pragma unroll
            for (int k = 0; k < 4; k++) acc[i][j][k] = 0.f;

    uint32_t fa[2][4];   // A prefetch, 2 tiles in flight (pre-packed bf16)

#define LOAD_TILE(T) do {                                                     \
        const float4* _p = aSrc4 + (size_t)(T) * (BK >> 2);                   \
        float4 _x = __ldg(_p), _y = __ldg(_p + 1);                            \
        uint32_t* _d = fa[(T) & 1];                                           \
        _d[0] = packbf2(_x.x, _x.y); _d[1] = packbf2(_x.z, _x.w);             \
        _d[2] = packbf2(_y.x, _y.y); _d[3] = packbf2(_y.z, _y.w);             \
    } while (0)

#define CONVERT_TILE(T) do {                                                  \
        const uint32_t _da = bAbf + (uint32_t)((T) & 1) * ABF_ST;             \
        uint32_t* _d = fa[(T) & 1];                                           \
        asm volatile("st.shared.v4.b32 [%0], {%1,%2,%3,%4};" ::               \
            "r"(_da + abfrel), "r"(_d[0]), "r"(_d[1]), "r"(_d[2]), "r"(_d[3]) \
            : "memory");                                                      \
    } while (0)

#define ISSUE_B_TILE(T, S) do {                                               \
        const uint32_t _bd = bB + (uint32_t)(S) * B_ST + brel0;               \
        const __nv_bfloat16* _bs = bsrc0 + (size_t)(T) * BK;                  \
        cp16(_bd,          _bs);                                              \
        cp16(_bd + 4096u,  _bs + 32 * K);                                     \
        cp16(_bd + 8192u,  _bs + 64 * K);                                     \
        cp16(_bd + 12288u, _bs + 96 * K);                                     \
    } while (0)

    // this warp's 2 K16 steps of one k-tile (R14 scheme, non-hoisted frags)
#define COMPUTE_TILE(AOFF, BOFF) do {                                         \
        _Pragma("unroll")                                                     \
        for (int _s = 0; _s < 2; _s++) {                                      \
            const int ks = ks0 + _s;                                          \
            uint32_t a[2][4], b[2][4];                                        \
            _Pragma("unroll")                                                 \
            for (int mi = 0; mi < 2; mi++) {                                  \
                int c = ks * 2 + achalf;                                      \
                ldmx4(a[mi], (AOFF) + (uint32_t)(arow[mi] * 8 + (c ^ (arow[mi] & 7))) * 16); \
            }                                                                 \
            _Pragma("unroll")                                                 \
            for (int nj = 0; nj < 2; nj++) {                                  \
                int c = ks * 2 + bchalf;                                      \
                ldmx4(b[nj], (BOFF) + (uint32_t)(brow[nj] * 8 + (c ^ (brow[nj] & 7))) * 16); \
            }                                                                 \
            _Pragma("unroll")                                                 \
            for (int mi = 0; mi < 2; mi++)                                    \
                _Pragma("unroll")                                             \
                for (int nt = 0; nt < 4; nt++)                                \
                    mma16816(acc[mi][nt], a[mi], &b[nt >> 1][(nt & 1) * 2]);  \
        }                                                                     \
    } while (0)

    // ---------- prologue ----------
    ISSUE_B_TILE(0, 0); CP_COMMIT();
    ISSUE_B_TILE(1, 1); CP_COMMIT();
    LOAD_TILE(0);
    LOAD_TILE(1);
    CONVERT_TILE(0);
    CP_WAIT1();               // B(0) complete (B(1) in flight)
    __syncthreads();

    // ---------- main loop: one barrier per tile; B depth 2 over 3 slots ----
    int sIss = 2, sCur = 0;   // slot indices mod 3
    for (int kt = 0; kt < NKT; kt++) {
        if (kt + 2 < NKT) {
            LOAD_TILE(kt + 2);            // into fa[kt&1] (tile kt converted)
            ISSUE_B_TILE(kt + 2, sIss);
        }
        CP_COMMIT();

        COMPUTE_TILE(bAbf + (uint32_t)(kt & 1) * ABF_ST,
                     bB + (uint32_t)sCur * B_ST);

        if (kt + 1 < NKT) CONVERT_TILE(kt + 1);   // own data; barrier publishes
        CP_WAIT1();                                // B(kt+1) complete
        __syncthreads();                           // publish Abf/B(kt+1); free kt

        sCur = (sCur == 2) ? 0 : sCur + 1;
        sIss = (sIss == 2) ? 0 : sIss + 1;
    }

    // ---------- partner merge (kh=0 -> kh=1) via smem, then epilogue ----------
    __syncthreads();   // B ring free
    const uint32_t xb = bB + (uint32_t)wt * 4096 + (uint32_t)lane * 4;
    if (kh == 0) {
#pragma unroll
        for (int mi = 0; mi < 2; mi++)
#pragma unroll
            for (int nt = 0; nt < 4; nt++)
#pragma unroll
                for (int k = 0; k < 4; k++) {
                    const int e = mi * 16 + nt * 4 + k;
                    asm volatile("st.shared.f32 [%0], %1;"
                                 :: "r"(xb + (uint32_t)e * 128), "f"(acc[mi][nt][k])
                                 : "memory");
                }
    }
    __syncthreads();

    if (kh == 1) {
        const float C = -0.75257498915995302f;   // -2.5 / log2(10)
#pragma unroll
        for (int mi = 0; mi < 2; mi++) {
            const size_t row0 = bm0 + mi * 16 + (lane >> 2);
#pragma unroll
            for (int nt = 0; nt < 4; nt++) {
                float part[4];
#pragma unroll
                for (int k = 0; k < 4; k++) {
                    const int e = mi * 16 + nt * 4 + k;
                    asm volatile("ld.shared.f32 %0, [%1];"
                                 : "=f"(part[k]) : "r"(xb + (uint32_t)e * 128));
                }
                const int col = wt * 32 + nt * 8 + (lane & 3) * 2;
                float2 v0, v1;
                v0.x = C * __log2f(acc[mi][nt][0] + part[0]);
                v0.y = C * __log2f(acc[mi][nt][1] + part[1]);
                v1.x = C * __log2f(acc[mi][nt][2] + part[2]);
                v1.y = C * __log2f(acc[mi][nt][3] + part[3]);
                *reinterpret_cast<float2*>(out + row0 * BN + col)       = v0;
                *reinterpret_cast<float2*>(out + (row0 + 8) * BN + col) = v1;
            }
        }
    }
}

extern "C" void kernel_launch(void* const* d_in, const int* in_sizes, int n_in,
                              void* d_out, int out_size) {
    const float* l_target = (const float*)d_in[0];   // [B, L] fp32
    const float* trans    = (const float*)d_in[1];   // [F, L] fp32
    const float* lam      = (const float*)d_in[2];   // [L]    fp32

    const int L = in_sizes[2];
    const int F = in_sizes[1] / L;   // 128
    const int B = in_sizes[0] / L;   // 8192
    float* out = (float*)d_out;

    cudaFuncSetAttribute(gemm_log_kernel<8192>,
                         cudaFuncAttributeMaxDynamicSharedMemorySize, DYN_SMEM);

    int total4 = (F * L) >> 2;
    wt_kernel<<<(total4 + 255) / 256, 256>>>(trans, lam, F, L);
    gemm_log_kernel<8192><<<B / BM, THREADS, DYN_SMEM>>>(l_target, out);
}